// round 16
// baseline (speedup 1.0000x reference)
#include <cuda_runtime.h>
#include <cuda_bf16.h>
#include <cstdint>

// ---------------- problem constants ----------------
#define BATCH 4
#define CH    256
#define HW    64
#define NPIX  (HW*HW)          // 4096
#define OHW   62
#define NP    (OHW*OHW)        // 3844
#define KCAT  768              // [ah|ah|al] x [bh|bl|bh]
#define EPSN  1e-12f

// ---------------- scratch ----------------
__device__ __nv_bfloat16 g_Acat[(size_t)BATCH*NPIX*KCAT];
__device__ __nv_bfloat16 g_Bcat[(size_t)BATCH*NPIX*KCAT];
__device__ float g_pnorm[BATCH*NPIX];
__device__ float g_psq  [BATCH*NPIX];
__device__ float g_tnorm[BATCH*NPIX];
__device__ float g_tsq  [BATCH*NPIX];
__device__ float g_D[(size_t)BATCH*NPIX*NPIX];             // 268 MB
__device__ unsigned long long g_pack[(size_t)BATCH*NP*OHW];
__device__ float g_lossacc;

// ---------------- helpers ----------------
__device__ __forceinline__ uint32_t s2u(const void* p) {
    uint32_t a;
    asm("{ .reg .u64 t; cvta.to.shared.u64 t, %1; cvt.u32.u64 %0, t; }" : "=r"(a) : "l"(p));
    return a;
}
__device__ __forceinline__ unsigned long long umax64(unsigned long long a, unsigned long long b) {
    return a > b ? a : b;
}

#define LDMATRIX_X4(r, addr) \
    asm volatile("ldmatrix.sync.aligned.m8n8.x4.shared.b16 {%0,%1,%2,%3}, [%4];" \
                 : "=r"((r)[0]), "=r"((r)[1]), "=r"((r)[2]), "=r"((r)[3]) : "r"(addr))

#define MMA16816(d, a, b0, b1) \
    asm volatile("mma.sync.aligned.m16n8k16.row.col.f32.bf16.bf16.f32 " \
                 "{%0,%1,%2,%3}, {%4,%5,%6,%7}, {%8,%9}, {%0,%1,%2,%3};" \
                 : "+f"((d)[0]), "+f"((d)[1]), "+f"((d)[2]), "+f"((d)[3]) \
                 : "r"((a)[0]), "r"((a)[1]), "r"((a)[2]), "r"((a)[3]), "r"(b0), "r"(b1))

// ---------------- K1: normalize + bf16-split + pack (single global read pass) ----------------
__global__ void __launch_bounds__(256) normalize_kernel(const float* __restrict__ xp,
                                                        const float* __restrict__ xt)
{
    __shared__ float red[8][32];
    __shared__ float rs[32];
    __shared__ __nv_bfloat16 stage[32][514];   // [h(256) | l(256) | pad2]

    if (blockIdx.x == 0 && blockIdx.y == 0 && threadIdx.x == 0)
        g_lossacc = 0.f;                       // reset accumulator every replay

    int which = blockIdx.y;
    const float* __restrict__ x = which ? xt : xp;
    float* __restrict__ nrm = which ? g_tnorm : g_pnorm;
    float* __restrict__ sq  = which ? g_tsq   : g_psq;

    int tx = threadIdx.x & 31, ty = threadIdx.x >> 5;
    int g0 = blockIdx.x * 32;
    int b  = g0 >> 12;
    int pix = (g0 & 4095) + tx;
    size_t base = (size_t)b * (CH*NPIX) + pix;

    float v[32];
    float s = 0.f;
    #pragma unroll
    for (int k = 0; k < 32; k++) {
        v[k] = x[base + (size_t)(ty*32 + k) * NPIX];
        s += v[k] * v[k];
    }
    red[ty][tx] = s;
    __syncthreads();
    if (ty == 0) {
        float tot = 0.f;
        #pragma unroll
        for (int j = 0; j < 8; j++) tot += red[j][tx];
        float n = sqrtf(tot);
        nrm[g0 + tx] = n;
        sq [g0 + tx] = tot;
        rs[tx] = 1.f / fmaxf(n, EPSN);
    }
    __syncthreads();
    float r = rs[tx];
    #pragma unroll
    for (int k = 0; k < 32; k++) {
        float f = v[k] * r;
        __nv_bfloat16 h = __float2bfloat16(f);
        __nv_bfloat16 l = __float2bfloat16(f - __bfloat162float(h));
        int c = ty*32 + k;
        stage[tx][c]       = h;
        stage[tx][256 + c] = l;
    }
    __syncthreads();

    int sel1 = which ? 1 : 0;   // pred [h,h,l]; targ [h,l,h]
    int sel2 = which ? 0 : 1;
    uint32_t* __restrict__ dst = (uint32_t*)(which ? g_Bcat : g_Acat);
    const uint32_t* __restrict__ src = (const uint32_t*)&stage[0][0];  // pitch 257 u32
    #pragma unroll
    for (int i = 0; i < 48; i++) {
        int f = threadIdx.x + i * 256;
        int row = f / 384;
        int rem = f - row * 384;
        int region = rem >> 7;
        int j = rem & 127;
        int sel = (region == 0) ? 0 : ((region == 1) ? sel1 : sel2);
        uint32_t val = src[row * 257 + sel * 128 + j];
        dst[(size_t)(g0 + row) * 384 + region * 128 + j] = val;
    }
}

// ---------------- K2: HMMA bf16 GEMM  D = Acat * Bcat^T  (4096x4096, K=768) ----------------
// 128x128 tile, 256 threads, 3-stage cp.async (96KB smem, 2 CTA/SM), 1 sync/chunk
#define TM 128
#define TN 128
#define BKC 64
#define NCHUNK (KCAT/BKC)     // 12
#define STAGE_BYTES 32768     // A 16K + B 16K
#define GEMM_SMEM (3*STAGE_BYTES)

static __device__ __forceinline__ void load_chunk(
    const __nv_bfloat16* __restrict__ A, const __nv_bfloat16* __restrict__ Bm,
    int u0, int v0, int c, uint32_t sdst, int tid)
{
    #pragma unroll
    for (int i = 0; i < 8; i++) {
        int f = tid + i * 256;
        int tile = f >> 10;
        int wi = f & 1023;
        int row = wi >> 3, c16 = wi & 7;
        uint32_t off = (uint32_t)((row << 7) | (c16 << 4));
        uint32_t sw = off ^ ((off >> 3) & 0x70);
        const __nv_bfloat16* src =
            (tile ? Bm : A) + (size_t)((tile ? v0 : u0) + row) * KCAT + c * BKC + c16 * 8;
        uint32_t daddr = sdst + tile * 16384 + sw;
        asm volatile("cp.async.cg.shared.global [%0], [%1], 16;" :: "r"(daddr), "l"(src));
    }
    asm volatile("cp.async.commit_group;");
}

__global__ void __launch_bounds__(256, 2) gemm_kernel()
{
    extern __shared__ char smem[];
    uint32_t sb = s2u(smem);
    int tid = threadIdx.x, wid = tid >> 5, lane = tid & 31;
    int b = blockIdx.z;
    int u0 = blockIdx.y * TM, v0 = blockIdx.x * TN;
    const __nv_bfloat16* A  = g_Acat + (size_t)b * NPIX * KCAT;
    const __nv_bfloat16* Bm = g_Bcat + (size_t)b * NPIX * KCAT;

    int wm = (wid & 1) * 64;
    int wn = (wid >> 1) * 32;

    float acc[4][4][4];
    #pragma unroll
    for (int mt = 0; mt < 4; mt++)
        #pragma unroll
        for (int nt = 0; nt < 4; nt++)
            #pragma unroll
            for (int e = 0; e < 4; e++) acc[mt][nt][e] = 0.f;

    uint32_t a_base[4], a_msk[4], b_base[2], b_msk[2];
    #pragma unroll
    for (int mt = 0; mt < 4; mt++) {
        int row = wm + mt*16 + (lane & 15);
        a_base[mt] = (uint32_t)(row * 128 + ((lane >> 4) * 16));
        a_msk[mt]  = (uint32_t)((row & 7) << 4);
    }
    #pragma unroll
    for (int g = 0; g < 2; g++) {
        int nt    = g*2 + ((lane >> 4) & 1);
        int khalf = (lane >> 3) & 1;
        int row   = wn + nt*8 + (lane & 7);
        b_base[g] = (uint32_t)(16384 + row * 128 + khalf * 16);
        b_msk[g]  = (uint32_t)((row & 7) << 4);
    }

    load_chunk(A, Bm, u0, v0, 0, sb,               tid);
    load_chunk(A, Bm, u0, v0, 1, sb + STAGE_BYTES, tid);

    #pragma unroll 1
    for (int c = 0; c < NCHUNK; c++) {
        // chunk c must be complete; chunks issued beyond c: 1 (c+1) except last iter
        if (c < NCHUNK - 1) asm volatile("cp.async.wait_group 1;");
        else                asm volatile("cp.async.wait_group 0;");
        __syncthreads();
        // slot (c+2)%3 == slot (c-1)%3: its readers finished before the barrier above
        if (c + 2 < NCHUNK)
            load_chunk(A, Bm, u0, v0, c + 2, sb + ((c + 2) % 3) * STAGE_BYTES, tid);

        uint32_t cbase = sb + (c % 3) * STAGE_BYTES;
        #pragma unroll
        for (int ks = 0; ks < 4; ks++) {
            uint32_t a_frag[4][4], b_frag[2][4];
            #pragma unroll
            for (int mt = 0; mt < 4; mt++)
                LDMATRIX_X4(a_frag[mt], cbase + ((a_base[mt] + ks*32) ^ a_msk[mt]));
            #pragma unroll
            for (int g = 0; g < 2; g++)
                LDMATRIX_X4(b_frag[g], cbase + ((b_base[g] + ks*32) ^ b_msk[g]));
            #pragma unroll
            for (int mt = 0; mt < 4; mt++)
                #pragma unroll
                for (int nt = 0; nt < 4; nt++)
                    MMA16816(acc[mt][nt], a_frag[mt],
                             b_frag[nt >> 1][(nt & 1) * 2],
                             b_frag[nt >> 1][(nt & 1) * 2 + 1]);
        }
    }

    float* __restrict__ Db = g_D + (size_t)b * NPIX * NPIX;
    int qrow = lane >> 2, qcol = (lane & 3) * 2;
    #pragma unroll
    for (int mt = 0; mt < 4; mt++) {
        #pragma unroll
        for (int nt = 0; nt < 4; nt++) {
            int r0  = u0 + wm + mt*16 + qrow;
            int col = v0 + wn + nt*8 + qcol;
            *(float2*)&Db[(size_t)r0       * NPIX + col] = make_float2(acc[mt][nt][0], acc[mt][nt][1]);
            *(float2*)&Db[(size_t)(r0 + 8) * NPIX + col] = make_float2(acc[mt][nt][2], acc[mt][nt][3]);
        }
    }
}

// ---------------- K3: segmented-ring diagonal score + per-(q,pr) argmax ----------------
#define SEGT 8
#define AM_RING_OFF   0                          // 3 * 4096 floats = 49152 B
#define AM_BSUM_OFF   (3*4096*4)                 // 64*66 floats = 16896 B
#define AM_RED_OFF    (AM_BSUM_OFF + 64*66*4)    // 4*64 u64 = 2048 B
#define AM_SMEM       (AM_RED_OFF + 4*64*8)      // 68096 B

static __device__ __forceinline__ void load_block(
    const float* __restrict__ Db, int qr0, int pr0, int k, uint32_t sdst, int tid)
{
    const float* bp = Db + (size_t)(qr0 + k) * 64 * NPIX + (pr0 + k) * 64;
    #pragma unroll
    for (int i = 0; i < 4; i++) {
        int idx = tid + i * 256;
        int row = idx >> 4, c4 = (idx & 15) << 2;
        const float* src = bp + (size_t)row * NPIX + c4;
        uint32_t daddr = sdst + (uint32_t)(row * 64 + c4) * 4;
        asm volatile("cp.async.cg.shared.global [%0], [%1], 16;" :: "r"(daddr), "l"(src));
    }
    asm volatile("cp.async.commit_group;");
}

__global__ void __launch_bounds__(256, 3) score_argmax_kernel()
{
    extern __shared__ char smem[];
    float* ring = (float*)(smem + AM_RING_OFF);
    float* Bsum = (float*)(smem + AM_BSUM_OFF);
    unsigned long long* red2 = (unsigned long long*)(smem + AM_RED_OFF);

    int x = blockIdx.x;                      // 0..122; s = 0,-1,1,-2,2,...
    int s = (x & 1) ? -((x + 1) >> 1) : (x >> 1);
    int b = blockIdx.z;
    int as = s < 0 ? -s : s;
    int len = OHW - as;
    int t0  = blockIdx.y * SEGT;
    if (t0 >= len) return;
    int nt = len - t0; if (nt > SEGT) nt = SEGT;

    int qr0 = (s > 0 ? s : 0) + t0;
    int pr0 = (s < 0 ? -s : 0) + t0;

    int tid = threadIdx.x;
    const float* __restrict__ Db = g_D + (size_t)b * NPIX * NPIX;
    uint32_t rbase = s2u(ring);

    load_block(Db, qr0, pr0, 0, rbase,             tid);
    load_block(Db, qr0, pr0, 1, rbase + 16384,     tid);
    load_block(Db, qr0, pr0, 2, rbase + 2 * 16384, tid);

    int qc  = tid & 63;
    int pcg = tid >> 6;

    #pragma unroll 1
    for (int t = 0; t < nt; t++) {
        asm volatile("cp.async.wait_group 0;");
        __syncthreads();

        const float* p0 = ring + (t % 3) * 4096;
        const float* p1 = ring + ((t + 1) % 3) * 4096;
        const float* p2 = ring + ((t + 2) % 3) * 4096;
        #pragma unroll
        for (int i = 0; i < 8; i++) {
            int e2 = tid + i * 256;
            int row = e2 >> 5, c2 = (e2 & 31) << 1;
            float2 a  = *(const float2*)(p0 + row * 64 + c2);
            float2 bb = *(const float2*)(p1 + row * 64 + c2);
            float2 cc = *(const float2*)(p2 + row * 64 + c2);
            *(float2*)(Bsum + row * 66 + c2) = make_float2(a.x + bb.x + cc.x, a.y + bb.y + cc.y);
        }
        __syncthreads();

        if (t + 3 <= nt + 1)
            load_block(Db, qr0, pr0, t + 3, rbase + (uint32_t)(t % 3) * 16384, tid);

        unsigned long long best = 0ULL;
        if (qc < OHW) {
            const float* B0 = Bsum + qc * 66;
            const float* B1 = Bsum + (qc + 1) * 66 + 1;
            const float* B2 = Bsum + (qc + 2) * 66 + 2;
            int pgb = (pr0 + t) * OHW;
            #pragma unroll
            for (int k = 0; k < 16; k++) {
                int pc = pcg + (k << 2);
                if (pc < OHW) {
                    float sc = B0[pc] + B1[pc] + B2[pc];
                    uint32_t u = __float_as_uint(sc);
                    u ^= (u & 0x80000000u) ? 0xFFFFFFFFu : 0x80000000u;
                    unsigned long long pk =
                        ((unsigned long long)u << 32) | (uint32_t)(0xFFFFFFFFu - (pgb + pc));
                    best = umax64(best, pk);
                }
            }
        }
        red2[pcg * 64 + qc] = best;
        __syncthreads();
        if (tid < OHW) {
            unsigned long long m = red2[tid];
            m = umax64(m, red2[64 + tid]);
            m = umax64(m, red2[128 + tid]);
            m = umax64(m, red2[192 + tid]);
            int bq = (b * OHW + (qr0 + t)) * OHW + tid;
            g_pack[(size_t)bq * OHW + (pr0 + t)] = m;
        }
        __syncthreads();
    }
}

// ---------------- K4: fused combine (argmax over pr) + closed-form MSE ----------------
__constant__ int c_doff[9] = {0,1,2,64,65,66,128,129,130};

__global__ void __launch_bounds__(256) combine_loss_kernel()
{
    int bq = blockIdx.x * 8 + (threadIdx.x >> 5);
    int lane = threadIdx.x & 31;
    __shared__ float cta_sum[8];

    float val = 0.f;
    if (bq < BATCH * NP) {
        unsigned long long m = 0ULL;
        if (lane < OHW)      m = g_pack[(size_t)bq * OHW + lane];
        if (lane + 32 < OHW) m = umax64(m, g_pack[(size_t)bq * OHW + lane + 32]);
        #pragma unroll
        for (int o = 16; o > 0; o >>= 1)
            m = umax64(m, __shfl_xor_sync(0xffffffffu, m, o));
        int match = (int)(0xFFFFFFFFu - (uint32_t)(m & 0xFFFFFFFFu));

        // loss terms: lanes 0..8 handle the 9 patch offsets
        int b = bq / NP;
        int q = bq - b * NP;
        if (lane < 9) {
            int qr = q / OHW, qc = q - qr * OHW;
            int mr = match / OHW, mc = match - mr * OHW;
            int d = c_doff[lane];
            int u = qr * HW + qc + d;
            int v = mr * HW + mc + d;
            int nb = b * NPIX;
            const float* __restrict__ Dq = g_D + (size_t)b * NPIX * NPIX;
            float cross = g_pnorm[nb + u] * g_tnorm[nb + v] * Dq[(size_t)u * NPIX + v];
            val = g_psq[nb + u] + g_tsq[nb + v] - 2.f * cross;
        }
    }
    #pragma unroll
    for (int o = 16; o > 0; o >>= 1)
        val += __shfl_xor_sync(0xffffffffu, val, o);
    if (lane == 0) cta_sum[threadIdx.x >> 5] = val;
    __syncthreads();
    if (threadIdx.x == 0) {
        float t = 0.f;
        #pragma unroll
        for (int w = 0; w < 8; w++) t += cta_sum[w];
        atomicAdd(&g_lossacc, t);
    }
}

// ---------------- K5: write scalar ----------------
__global__ void finalize_kernel(float* __restrict__ out)
{
    out[0] = g_lossacc * (1.f / 35426304.f);   // 4*3844*256*9
}

// ---------------- launch ----------------
extern "C" void kernel_launch(void* const* d_in, const int* in_sizes, int n_in,
                              void* d_out, int out_size)
{
    const float* pred = (const float*)d_in[0];
    const float* targ = (const float*)d_in[1];
    float* out = (float*)d_out;

    static int smem_set = 0;
    if (!smem_set) {
        cudaFuncSetAttribute(gemm_kernel, cudaFuncAttributeMaxDynamicSharedMemorySize, GEMM_SMEM);
        cudaFuncSetAttribute(score_argmax_kernel, cudaFuncAttributeMaxDynamicSharedMemorySize, AM_SMEM);
        smem_set = 1;
    }

    normalize_kernel<<<dim3(512, 2), 256>>>(pred, targ);

    dim3 ggrid(NPIX / TN, NPIX / TM, BATCH);   // 32 x 32 x 4
    gemm_kernel<<<ggrid, 256, GEMM_SMEM>>>();

    dim3 agrid(123, 8, BATCH);                 // chains x segments x batch
    score_argmax_kernel<<<agrid, 256, AM_SMEM>>>();

    combine_loss_kernel<<<(BATCH * NP + 7) / 8, 256>>>();
    finalize_kernel<<<1, 1>>>(out);
}

// round 17
// speedup vs baseline: 1.5533x; 1.5533x over previous
#include <cuda_runtime.h>
#include <cuda_bf16.h>
#include <cstdint>

// ---------------- problem constants ----------------
#define BATCH 4
#define CH    256
#define HW    64
#define NPIX  (HW*HW)          // 4096
#define OHW   62
#define NP    (OHW*OHW)        // 3844
#define KCAT  768              // [ah|ah|al] x [bh|bl|bh]
#define EPSN  1e-12f

// ---------------- scratch ----------------
__device__ __nv_bfloat16 g_Acat[(size_t)BATCH*NPIX*KCAT];
__device__ __nv_bfloat16 g_Bcat[(size_t)BATCH*NPIX*KCAT];
__device__ float g_pnorm[BATCH*NPIX];
__device__ float g_psq  [BATCH*NPIX];
__device__ float g_tnorm[BATCH*NPIX];
__device__ float g_tsq  [BATCH*NPIX];
__device__ float g_D[(size_t)BATCH*NPIX*NPIX];             // 268 MB
__device__ unsigned long long g_pack[(size_t)BATCH*NP*OHW];
__device__ float g_lossacc;

// ---------------- helpers ----------------
__device__ __forceinline__ uint32_t s2u(const void* p) {
    uint32_t a;
    asm("{ .reg .u64 t; cvta.to.shared.u64 t, %1; cvt.u32.u64 %0, t; }" : "=r"(a) : "l"(p));
    return a;
}
__device__ __forceinline__ unsigned long long umax64(unsigned long long a, unsigned long long b) {
    return a > b ? a : b;
}

#define LDMATRIX_X4(r, addr) \
    asm volatile("ldmatrix.sync.aligned.m8n8.x4.shared.b16 {%0,%1,%2,%3}, [%4];" \
                 : "=r"((r)[0]), "=r"((r)[1]), "=r"((r)[2]), "=r"((r)[3]) : "r"(addr))

#define MMA16816(d, a, b0, b1) \
    asm volatile("mma.sync.aligned.m16n8k16.row.col.f32.bf16.bf16.f32 " \
                 "{%0,%1,%2,%3}, {%4,%5,%6,%7}, {%8,%9}, {%0,%1,%2,%3};" \
                 : "+f"((d)[0]), "+f"((d)[1]), "+f"((d)[2]), "+f"((d)[3]) \
                 : "r"((a)[0]), "r"((a)[1]), "r"((a)[2]), "r"((a)[3]), "r"(b0), "r"(b1))

// ---------------- K1: normalize + bf16-split + pack (R15 two-read version) ----------------
__global__ void __launch_bounds__(256) normalize_kernel(const float* __restrict__ xp,
                                                        const float* __restrict__ xt)
{
    __shared__ float red[8][32];
    __shared__ float rs[32];
    __shared__ __nv_bfloat16 stage[32][514];   // [h(256) | l(256) | pad2]

    if (blockIdx.x == 0 && blockIdx.y == 0 && threadIdx.x == 0)
        g_lossacc = 0.f;                       // reset accumulator every replay

    int which = blockIdx.y;
    const float* __restrict__ x = which ? xt : xp;
    float* __restrict__ nrm = which ? g_tnorm : g_pnorm;
    float* __restrict__ sq  = which ? g_tsq   : g_psq;

    int tx = threadIdx.x & 31, ty = threadIdx.x >> 5;
    int g0 = blockIdx.x * 32;
    int b  = g0 >> 12;
    int pix = (g0 & 4095) + tx;
    size_t base = (size_t)b * (CH*NPIX) + pix;

    float s = 0.f;
    #pragma unroll
    for (int k = 0; k < 32; k++) {
        float v = x[base + (size_t)(ty*32 + k) * NPIX];
        s += v * v;
    }
    red[ty][tx] = s;
    __syncthreads();
    if (ty == 0) {
        float tot = 0.f;
        #pragma unroll
        for (int j = 0; j < 8; j++) tot += red[j][tx];
        float n = sqrtf(tot);
        nrm[g0 + tx] = n;
        sq [g0 + tx] = tot;
        rs[tx] = 1.f / fmaxf(n, EPSN);
    }
    __syncthreads();
    float r = rs[tx];
    #pragma unroll
    for (int k = 0; k < 32; k++) {
        float f = x[base + (size_t)(ty*32 + k) * NPIX] * r;
        __nv_bfloat16 h = __float2bfloat16(f);
        __nv_bfloat16 l = __float2bfloat16(f - __bfloat162float(h));
        int c = ty*32 + k;
        stage[tx][c]       = h;
        stage[tx][256 + c] = l;
    }
    __syncthreads();

    int sel1 = which ? 1 : 0;   // pred [h,h,l]; targ [h,l,h]
    int sel2 = which ? 0 : 1;
    uint32_t* __restrict__ dst = (uint32_t*)(which ? g_Bcat : g_Acat);
    const uint32_t* __restrict__ src = (const uint32_t*)&stage[0][0];  // pitch 257 u32
    #pragma unroll
    for (int i = 0; i < 48; i++) {
        int f = threadIdx.x + i * 256;
        int row = f / 384;
        int rem = f - row * 384;
        int region = rem >> 7;
        int j = rem & 127;
        int sel = (region == 0) ? 0 : ((region == 1) ? sel1 : sel2);
        uint32_t val = src[row * 257 + sel * 128 + j];
        dst[(size_t)(g0 + row) * 384 + region * 128 + j] = val;
    }
}

// ---------------- K2: HMMA bf16 GEMM (R15 known-good: 128x128, 2-stage, 2 CTA/SM) ----------------
#define TM 128
#define TN 128
#define BKC 64
#define NCHUNK (KCAT/BKC)     // 12
#define STAGE_BYTES 32768     // A 16K + B 16K
#define GEMM_SMEM (2*STAGE_BYTES)

static __device__ __forceinline__ void load_chunk(
    const __nv_bfloat16* __restrict__ A, const __nv_bfloat16* __restrict__ Bm,
    int u0, int v0, int c, uint32_t sdst, int tid)
{
    #pragma unroll
    for (int i = 0; i < 8; i++) {
        int f = tid + i * 256;
        int tile = f >> 10;
        int wi = f & 1023;
        int row = wi >> 3, c16 = wi & 7;
        uint32_t off = (uint32_t)((row << 7) | (c16 << 4));
        uint32_t sw = off ^ ((off >> 3) & 0x70);
        const __nv_bfloat16* src =
            (tile ? Bm : A) + (size_t)((tile ? v0 : u0) + row) * KCAT + c * BKC + c16 * 8;
        uint32_t daddr = sdst + tile * 16384 + sw;
        asm volatile("cp.async.cg.shared.global [%0], [%1], 16;" :: "r"(daddr), "l"(src));
    }
    asm volatile("cp.async.commit_group;");
}

__global__ void __launch_bounds__(256, 2) gemm_kernel()
{
    extern __shared__ char smem[];
    uint32_t sb = s2u(smem);
    int tid = threadIdx.x, wid = tid >> 5, lane = tid & 31;
    int b = blockIdx.z;
    int u0 = blockIdx.y * TM, v0 = blockIdx.x * TN;
    const __nv_bfloat16* A  = g_Acat + (size_t)b * NPIX * KCAT;
    const __nv_bfloat16* Bm = g_Bcat + (size_t)b * NPIX * KCAT;

    int wm = (wid & 1) * 64;
    int wn = (wid >> 1) * 32;

    float acc[4][4][4];
    #pragma unroll
    for (int mt = 0; mt < 4; mt++)
        #pragma unroll
        for (int nt = 0; nt < 4; nt++)
            #pragma unroll
            for (int e = 0; e < 4; e++) acc[mt][nt][e] = 0.f;

    uint32_t a_base[4], a_msk[4], b_base[2], b_msk[2];
    #pragma unroll
    for (int mt = 0; mt < 4; mt++) {
        int row = wm + mt*16 + (lane & 15);
        a_base[mt] = (uint32_t)(row * 128 + ((lane >> 4) * 16));
        a_msk[mt]  = (uint32_t)((row & 7) << 4);
    }
    #pragma unroll
    for (int g = 0; g < 2; g++) {
        int nt    = g*2 + ((lane >> 4) & 1);
        int khalf = (lane >> 3) & 1;
        int row   = wn + nt*8 + (lane & 7);
        b_base[g] = (uint32_t)(16384 + row * 128 + khalf * 16);
        b_msk[g]  = (uint32_t)((row & 7) << 4);
    }

    load_chunk(A, Bm, u0, v0, 0, sb, tid);

    #pragma unroll 1
    for (int c = 0; c < NCHUNK; c++) {
        int s = c & 1;
        if (c + 1 < NCHUNK) {
            load_chunk(A, Bm, u0, v0, c + 1, sb + (s ^ 1) * STAGE_BYTES, tid);
            asm volatile("cp.async.wait_group 1;");
        } else {
            asm volatile("cp.async.wait_group 0;");
        }
        __syncthreads();

        uint32_t cbase = sb + s * STAGE_BYTES;
        #pragma unroll
        for (int ks = 0; ks < 4; ks++) {
            uint32_t a_frag[4][4], b_frag[2][4];
            #pragma unroll
            for (int mt = 0; mt < 4; mt++)
                LDMATRIX_X4(a_frag[mt], cbase + ((a_base[mt] + ks*32) ^ a_msk[mt]));
            #pragma unroll
            for (int g = 0; g < 2; g++)
                LDMATRIX_X4(b_frag[g], cbase + ((b_base[g] + ks*32) ^ b_msk[g]));
            #pragma unroll
            for (int mt = 0; mt < 4; mt++)
                #pragma unroll
                for (int nt = 0; nt < 4; nt++)
                    MMA16816(acc[mt][nt], a_frag[mt],
                             b_frag[nt >> 1][(nt & 1) * 2],
                             b_frag[nt >> 1][(nt & 1) * 2 + 1]);
        }
        __syncthreads();
    }

    float* __restrict__ Db = g_D + (size_t)b * NPIX * NPIX;
    int qrow = lane >> 2, qcol = (lane & 3) * 2;
    #pragma unroll
    for (int mt = 0; mt < 4; mt++) {
        #pragma unroll
        for (int nt = 0; nt < 4; nt++) {
            int r0  = u0 + wm + mt*16 + qrow;
            int col = v0 + wn + nt*8 + qcol;
            *(float2*)&Db[(size_t)r0       * NPIX + col] = make_float2(acc[mt][nt][0], acc[mt][nt][1]);
            *(float2*)&Db[(size_t)(r0 + 8) * NPIX + col] = make_float2(acc[mt][nt][2], acc[mt][nt][3]);
        }
    }
}

// ---------------- K3: segmented-ring diagonal score + per-(q,pr) argmax ----------------
#define SEGT 8
#define AM_RING_OFF   0                          // 3 * 4096 floats = 49152 B
#define AM_BSUM_OFF   (3*4096*4)                 // 64*66 floats = 16896 B
#define AM_RED_OFF    (AM_BSUM_OFF + 64*66*4)    // 4*64 u64 = 2048 B
#define AM_SMEM       (AM_RED_OFF + 4*64*8)      // 68096 B

static __device__ __forceinline__ void load_block(
    const float* __restrict__ Db, int qr0, int pr0, int k, uint32_t sdst, int tid)
{
    const float* bp = Db + (size_t)(qr0 + k) * 64 * NPIX + (pr0 + k) * 64;
    #pragma unroll
    for (int i = 0; i < 4; i++) {
        int idx = tid + i * 256;
        int row = idx >> 4, c4 = (idx & 15) << 2;
        const float* src = bp + (size_t)row * NPIX + c4;
        uint32_t daddr = sdst + (uint32_t)(row * 64 + c4) * 4;
        asm volatile("cp.async.cg.shared.global [%0], [%1], 16;" :: "r"(daddr), "l"(src));
    }
    asm volatile("cp.async.commit_group;");
}

__global__ void __launch_bounds__(256, 3) score_argmax_kernel()
{
    extern __shared__ char smem[];
    float* ring = (float*)(smem + AM_RING_OFF);
    float* Bsum = (float*)(smem + AM_BSUM_OFF);
    unsigned long long* red2 = (unsigned long long*)(smem + AM_RED_OFF);

    int x = blockIdx.x;                      // 0..122; s = 0,-1,1,-2,2,...
    int s = (x & 1) ? -((x + 1) >> 1) : (x >> 1);
    int b = blockIdx.z;
    int as = s < 0 ? -s : s;
    int len = OHW - as;
    int t0  = blockIdx.y * SEGT;
    if (t0 >= len) return;
    int nt = len - t0; if (nt > SEGT) nt = SEGT;

    int qr0 = (s > 0 ? s : 0) + t0;
    int pr0 = (s < 0 ? -s : 0) + t0;

    int tid = threadIdx.x;
    const float* __restrict__ Db = g_D + (size_t)b * NPIX * NPIX;
    uint32_t rbase = s2u(ring);

    load_block(Db, qr0, pr0, 0, rbase,             tid);
    load_block(Db, qr0, pr0, 1, rbase + 16384,     tid);
    load_block(Db, qr0, pr0, 2, rbase + 2 * 16384, tid);

    int qc  = tid & 63;
    int pcg = tid >> 6;

    #pragma unroll 1
    for (int t = 0; t < nt; t++) {
        asm volatile("cp.async.wait_group 0;");
        __syncthreads();

        const float* p0 = ring + (t % 3) * 4096;
        const float* p1 = ring + ((t + 1) % 3) * 4096;
        const float* p2 = ring + ((t + 2) % 3) * 4096;
        #pragma unroll
        for (int i = 0; i < 8; i++) {
            int e2 = tid + i * 256;
            int row = e2 >> 5, c2 = (e2 & 31) << 1;
            float2 a  = *(const float2*)(p0 + row * 64 + c2);
            float2 bb = *(const float2*)(p1 + row * 64 + c2);
            float2 cc = *(const float2*)(p2 + row * 64 + c2);
            *(float2*)(Bsum + row * 66 + c2) = make_float2(a.x + bb.x + cc.x, a.y + bb.y + cc.y);
        }
        __syncthreads();

        if (t + 3 <= nt + 1)
            load_block(Db, qr0, pr0, t + 3, rbase + (uint32_t)(t % 3) * 16384, tid);

        unsigned long long best = 0ULL;
        if (qc < OHW) {
            const float* B0 = Bsum + qc * 66;
            const float* B1 = Bsum + (qc + 1) * 66 + 1;
            const float* B2 = Bsum + (qc + 2) * 66 + 2;
            int pgb = (pr0 + t) * OHW;
            #pragma unroll
            for (int k = 0; k < 16; k++) {
                int pc = pcg + (k << 2);
                if (pc < OHW) {
                    float sc = B0[pc] + B1[pc] + B2[pc];
                    uint32_t u = __float_as_uint(sc);
                    u ^= (u & 0x80000000u) ? 0xFFFFFFFFu : 0x80000000u;
                    unsigned long long pk =
                        ((unsigned long long)u << 32) | (uint32_t)(0xFFFFFFFFu - (pgb + pc));
                    best = umax64(best, pk);
                }
            }
        }
        red2[pcg * 64 + qc] = best;
        __syncthreads();
        if (tid < OHW) {
            unsigned long long m = red2[tid];
            m = umax64(m, red2[64 + tid]);
            m = umax64(m, red2[128 + tid]);
            m = umax64(m, red2[192 + tid]);
            int bq = (b * OHW + (qr0 + t)) * OHW + tid;
            g_pack[(size_t)bq * OHW + (pr0 + t)] = m;
        }
        __syncthreads();
    }
}

// ---------------- K4: fused combine (argmax over pr) + closed-form MSE ----------------
__constant__ int c_doff[9] = {0,1,2,64,65,66,128,129,130};

__global__ void __launch_bounds__(256) combine_loss_kernel()
{
    int bq = blockIdx.x * 8 + (threadIdx.x >> 5);
    int lane = threadIdx.x & 31;
    __shared__ float cta_sum[8];

    float val = 0.f;
    if (bq < BATCH * NP) {
        unsigned long long m = 0ULL;
        if (lane < OHW)      m = g_pack[(size_t)bq * OHW + lane];
        if (lane + 32 < OHW) m = umax64(m, g_pack[(size_t)bq * OHW + lane + 32]);
        #pragma unroll
        for (int o = 16; o > 0; o >>= 1)
            m = umax64(m, __shfl_xor_sync(0xffffffffu, m, o));
        int match = (int)(0xFFFFFFFFu - (uint32_t)(m & 0xFFFFFFFFu));

        int b = bq / NP;
        int q = bq - b * NP;
        if (lane < 9) {
            int qr = q / OHW, qc = q - qr * OHW;
            int mr = match / OHW, mc = match - mr * OHW;
            int d = c_doff[lane];
            int u = qr * HW + qc + d;
            int v = mr * HW + mc + d;
            int nb = b * NPIX;
            const float* __restrict__ Dq = g_D + (size_t)b * NPIX * NPIX;
            float cross = g_pnorm[nb + u] * g_tnorm[nb + v] * Dq[(size_t)u * NPIX + v];
            val = g_psq[nb + u] + g_tsq[nb + v] - 2.f * cross;
        }
    }
    #pragma unroll
    for (int o = 16; o > 0; o >>= 1)
        val += __shfl_xor_sync(0xffffffffu, val, o);
    if (lane == 0) cta_sum[threadIdx.x >> 5] = val;
    __syncthreads();
    if (threadIdx.x == 0) {
        float t = 0.f;
        #pragma unroll
        for (int w = 0; w < 8; w++) t += cta_sum[w];
        atomicAdd(&g_lossacc, t);
    }
}

// ---------------- K5: write scalar ----------------
__global__ void finalize_kernel(float* __restrict__ out)
{
    out[0] = g_lossacc * (1.f / 35426304.f);   // 4*3844*256*9
}

// ---------------- launch ----------------
extern "C" void kernel_launch(void* const* d_in, const int* in_sizes, int n_in,
                              void* d_out, int out_size)
{
    const float* pred = (const float*)d_in[0];
    const float* targ = (const float*)d_in[1];
    float* out = (float*)d_out;

    static int smem_set = 0;
    if (!smem_set) {
        cudaFuncSetAttribute(gemm_kernel, cudaFuncAttributeMaxDynamicSharedMemorySize, GEMM_SMEM);
        cudaFuncSetAttribute(score_argmax_kernel, cudaFuncAttributeMaxDynamicSharedMemorySize, AM_SMEM);
        smem_set = 1;
    }

    normalize_kernel<<<dim3(512, 2), 256>>>(pred, targ);

    dim3 ggrid(NPIX / TN, NPIX / TM, BATCH);   // 32 x 32 x 4
    gemm_kernel<<<ggrid, 256, GEMM_SMEM>>>();

    dim3 agrid(123, 8, BATCH);                 // chains x segments x batch
    score_argmax_kernel<<<agrid, 256, AM_SMEM>>>();

    combine_loss_kernel<<<(BATCH * NP + 7) / 8, 256>>>();
    finalize_kernel<<<1, 1>>>(out);
}